// round 7
// baseline (speedup 1.0000x reference)
#include <cuda_runtime.h>
#include <math.h>

// Problem constants (fixed by the reference setup)
#define BB   256
#define NA   24      // atoms
#define NN   23      // neighbors per atom (N-1)
#define NP   253     // pairs = NN*(NN-1)/2
#define KR   16
#define KA   32
#define NF   (KR + KA)
#define RCR  5.2f
#define RCA  3.5f
#define PI_F 3.14159265358979323846f
#define LOG2E 1.4426950408889634f
#define MAXT 8

#define PSTR 264     // pow_t row stride in floats (264 % 32 == 8  -> staggered banks)
#define RSTR 260     // radf_t row stride in floats (260 % 32 == 4 -> staggered banks)
#define SCALE_UP 100.0f
#define SCALE_DN 7.888609052210118e-31f   // 2^-100

typedef unsigned long long u64;

static __device__ __forceinline__ float ex2_approx(float x) {
    float r; asm("ex2.approx.ftz.f32 %0, %1;" : "=f"(r) : "f"(x)); return r;
}
static __device__ __forceinline__ float lg2_approx(float x) {
    float r; asm("lg2.approx.ftz.f32 %0, %1;" : "=f"(r) : "f"(x)); return r;
}
// ---- packed f32x2 helpers (sm_103a; ptxas never emits these from C++) ----
static __device__ __forceinline__ u64 pack2(float lo, float hi) {
    u64 r; asm("mov.b64 %0, {%1, %2};" : "=l"(r) : "f"(lo), "f"(hi)); return r;
}
static __device__ __forceinline__ void unpack2(u64 v, float& lo, float& hi) {
    asm("mov.b64 {%0, %1}, %2;" : "=f"(lo), "=f"(hi) : "l"(v));
}
static __device__ __forceinline__ u64 mul2(u64 a, u64 b) {
    u64 d; asm("mul.rn.f32x2 %0, %1, %2;" : "=l"(d) : "l"(a), "l"(b)); return d;
}
static __device__ __forceinline__ u64 fma2v(u64 a, u64 b, u64 c) {
    u64 d; asm("fma.rn.f32x2 %0, %1, %2, %3;" : "=l"(d) : "l"(a), "l"(b), "l"(c)); return d;
}

// Compile-time pair table: pair p -> (r | c<<8), rows of triu_indices(NN, k=1)
struct PT { unsigned short v[256]; };
static constexpr PT make_pt() {
    PT t{};
    int p = 0;
    for (int r = 0; r < NN; ++r)
        for (int c = r + 1; c < NN; ++c) { t.v[p] = (unsigned short)(r | (c << 8)); ++p; }
    for (; p < 256; ++p) t.v[p] = (unsigned short)(0 | (1 << 8));  // padding pairs
    return t;
}
static __device__ const PT d_pt = make_pt();

// Per-atom-type derived constants (filled by ani_param_kernel)
struct FastTab {
    float etaR[KR], shfR[KR];
    float cp[4], sp[4];          // cos/sin of the 4 distinct ShfA values
    float s0, eA, c1, rr0;       // ladder: u=dz-s0; A=2^(-eA u^2); R=2^(c1 u); rr0 first ratio
    float S[6];                  // S_z = rr_z * rr_{z+1}  (z+2 ladder step factors)
    float outscale;              // 2^(1-zeta)  (uniform in fast path)
    int   fast;
    // fallback (generic) parameters
    float cosA[KA], sinA[KA], zeta[KA], shfZ[KA], etaA2[KA], two2[KA];
};
static __device__ FastTab d_tab[MAXT];

__global__ void ani_param_kernel(const float* __restrict__ EtaR,
                                 const float* __restrict__ ShfR,
                                 const float* __restrict__ Zeta,
                                 const float* __restrict__ ShfZ,
                                 const float* __restrict__ EtaA,
                                 const float* __restrict__ ShfA)
{
    const int t = blockIdx.x;
    const int k = threadIdx.x;     // 32 threads
    FastTab& tb = d_tab[t];
    __shared__ int okflag;
    if (k == 0) okflag = 1;
    __syncthreads();

    if (k < KA) {
        float a = ShfA[t * KA + k];
        float s, c; sincosf(a, &s, &c);
        tb.cosA[k] = c;  tb.sinA[k] = s;
        float z = Zeta[t * KA + k];
        tb.zeta[k]  = z;
        tb.two2[k]  = exp2f(1.0f - z);
        tb.shfZ[k]  = ShfZ[t * KA + k];
        tb.etaA2[k] = -EtaA[t * KA + k] * LOG2E;
        float sz0 = ShfZ[t * KA];
        float dlt = (ShfZ[t * KA + 7] - sz0) * (1.0f / 7.0f);
        bool ok = (z == 32.0f)
               && (EtaA[t * KA + k] == EtaA[t * KA])
               && (ShfA[t * KA + k] == ShfA[t * KA + (k & ~7)])
               && (ShfZ[t * KA + k] == ShfZ[t * KA + (k & 7)])
               && (fabsf(ShfZ[t * KA + (k & 7)] - (sz0 + (float)(k & 7) * dlt)) < 1e-4f);
        if (!ok) okflag = 0;
    }
    if (k < KR) { tb.etaR[k] = EtaR[t * KR + k]; tb.shfR[k] = ShfR[t * KR + k]; }
    __syncthreads();
    if (k == 0) {
        tb.fast = okflag;
        float sz0 = ShfZ[t * KA];
        float dlt = (ShfZ[t * KA + 7] - sz0) * (1.0f / 7.0f);
        float eA  = EtaA[t * KA] * LOG2E;
        tb.s0 = sz0; tb.eA = eA; tb.c1 = 2.0f * eA * dlt;
        float ed2 = eA * dlt * dlt;
        float rr[7];
        for (int z = 0; z < 7; ++z) rr[z] = exp2f(-ed2 * (float)(2 * z + 1));
        tb.rr0 = rr[0];
        for (int z = 0; z < 6; ++z) tb.S[z] = rr[z] * rr[z + 1];
        tb.outscale = exp2f(1.0f - Zeta[t * KA]);
        for (int a = 0; a < 4; ++a) {
            float s, c; sincosf(ShfA[t * KA + a * 8], &s, &c);
            tb.cp[a] = c; tb.sp[a] = s;
        }
    }
}

__global__ __launch_bounds__(256)
void ani_feature_kernel(const float* __restrict__ coords,     // (B, NA, 3)
                        const int*   __restrict__ atom_types, // (NA,)
                        float*       __restrict__ out)        // (B, NA, 48)
{
    const int site = blockIdx.x;           // b * NA + i
    const int b = site / NA;
    const int i = site - b * NA;
    const int tid = threadIdx.x;
    const int w = tid >> 5;
    const int l = tid & 31;

    __shared__ float rxs[NN], rys[NN], rzs[NN];
    __shared__ float dsh[NN], invd[NN], fRsh[NN], fAsh[NN];
    __shared__ float cosAs[KA], sinAs[KA], zetas[KA], shfZs[KA], etaA2s[KA], two2s[KA];
    __shared__ float g2part[8][KR];
    __shared__ float g3part[8][KA];
    __shared__ __align__(16) float pow_t[4 * PSTR];   // (1+cos(theta-a))^32, row a
    __shared__ __align__(16) float radf_t[8 * RSTR];  // exp(-eta(dz-s_z)^2)*fw, row z

    const int ti = atom_types[i];          // uniform broadcast LDG
    const FastTab& tb = d_tab[ti];
    const int fast = tb.fast;

    // ---- Phase 1: neighbor geometry (threads 0..22) ----
    if (tid < NN) {
        const int j = (tid < i) ? tid : tid + 1;
        const float* ci = coords + (size_t)(b * NA + i) * 3;
        const float* cj = coords + (size_t)(b * NA + j) * 3;
        float rx = ci[0] - cj[0];
        float ry = ci[1] - cj[1];
        float rz = ci[2] - cj[2];
        float d  = sqrtf(rx * rx + ry * ry + rz * rz);
        rxs[tid] = rx; rys[tid] = ry; rzs[tid] = rz;
        dsh[tid] = d;
        invd[tid] = __frcp_rn(d);
        fRsh[tid] = 0.5f * (cosf(d * (PI_F / RCR)) + 1.0f);
        fAsh[tid] = 0.5f * (cosf(d * (PI_F / RCA)) + 1.0f);
    }
    // Fallback: stage generic parameter tables into shared (rare path)
    if (!fast) {
        for (int k = tid; k < KA; k += 256) {
            cosAs[k] = tb.cosA[k];  sinAs[k] = tb.sinA[k];
            zetas[k] = tb.zeta[k];  shfZs[k] = tb.shfZ[k];
            etaA2s[k] = tb.etaA2[k]; two2s[k] = tb.two2[k];
        }
    }
    __syncthreads();

    // ---- Phase 2: radial G2 (per-warp partials) ----
    if (l < KR) {
        const float er = tb.etaR[l], sr = tb.shfR[l];
        float acc2 = 0.0f;
        for (int j = w; j < NN; j += 8) {
            float t = dsh[j] - sr;
            acc2 += __expf(-er * t * t) * fRsh[j];
        }
        g2part[w][l] = acc2;
    }

    // ---- Phase 3: per-pair geometry + specials (1 thread = 1 pair) ----
    {
        const int p = tid;                          // 0..255; 253..255 padding (fw = 0)
        const unsigned short rc = d_pt.v[p];
        const int r = rc & 0xFF, c = rc >> 8;
        float d1 = dsh[r], d2 = dsh[c];
        float dot = rxs[r] * rxs[c] + rys[r] * rys[c] + rzs[r] * rzs[c];
        float cs = dot * invd[r] * invd[c];
        cs = fminf(fmaxf(cs, -1.0f + 1e-7f), 1.0f - 1e-7f);
        float sn = sqrtf(fmaxf(0.0f, 1.0f - cs * cs));
        float dz = 0.5f * (d1 + d2);
        float fw = (p < NP) ? fAsh[r] * fAsh[c] : 0.0f;

        if (fast) {
            // 4 angular powers (1+cos(theta-a))^32 via packed repeated squaring
            const u64 ONE2 = 0x3f8000003f800000ULL;
            u64 cs2 = pack2(cs, cs), sn2 = pack2(sn, sn);
            u64 cp01 = pack2(tb.cp[0], tb.cp[1]), cp23 = pack2(tb.cp[2], tb.cp[3]);
            u64 sp01 = pack2(tb.sp[0], tb.sp[1]), sp23 = pack2(tb.sp[2], tb.sp[3]);
            u64 x01 = fma2v(cs2, cp01, fma2v(sn2, sp01, ONE2));
            u64 x23 = fma2v(cs2, cp23, fma2v(sn2, sp23, ONE2));
            x01 = mul2(x01, x01); x01 = mul2(x01, x01); x01 = mul2(x01, x01);
            x01 = mul2(x01, x01); x01 = mul2(x01, x01);
            x23 = mul2(x23, x23); x23 = mul2(x23, x23); x23 = mul2(x23, x23);
            x23 = mul2(x23, x23); x23 = mul2(x23, x23);
            float p0, p1, p2, p3;
            unpack2(x01, p0, p1); unpack2(x23, p2, p3);
            pow_t[0 * PSTR + p] = p0;  pow_t[1 * PSTR + p] = p1;
            pow_t[2 * PSTR + p] = p2;  pow_t[3 * PSTR + p] = p3;

            // 8 radial envelopes: 2^100-scaled geometric ladder, z+2 packed steps
            float u = dz - tb.s0;
            float A = ex2_approx(fmaf(-tb.eA * u, u, SCALE_UP));
            float R = ex2_approx(tb.c1 * u);
            float unsc = fw * SCALE_DN;
            float v0 = A * unsc;
            float v1 = v0 * R * tb.rr0;
            float R2 = R * R;
            u64 v01 = pack2(v0, v1);
            u64 v23 = mul2(v01, pack2(R2 * tb.S[0], R2 * tb.S[1]));
            u64 v45 = mul2(v23, pack2(R2 * tb.S[2], R2 * tb.S[3]));
            u64 v67 = mul2(v45, pack2(R2 * tb.S[4], R2 * tb.S[5]));
            float f2, f3, f4, f5, f6, f7;
            unpack2(v23, f2, f3); unpack2(v45, f4, f5); unpack2(v67, f6, f7);
            radf_t[0 * RSTR + p] = v0;  radf_t[1 * RSTR + p] = v1;
            radf_t[2 * RSTR + p] = f2;  radf_t[3 * RSTR + p] = f3;
            radf_t[4 * RSTR + p] = f4;  radf_t[5 * RSTR + p] = f5;
            radf_t[6 * RSTR + p] = f6;  radf_t[7 * RSTR + p] = f7;
        } else {
            reinterpret_cast<float4*>(radf_t)[p] = make_float4(cs, sn, dz, fw);
        }
    }
    __syncthreads();

    // ---- Phase 4: angular accumulation ----
    {
        float acc = 0.0f;
        if (fast) {
            // lane l = feature (a = l/8, z = l%8); warp w covers pairs [32w, 32w+32)
            const ulonglong2* pp = reinterpret_cast<const ulonglong2*>(pow_t  + (l >> 3) * PSTR) + w * 8;
            const ulonglong2* rp = reinterpret_cast<const ulonglong2*>(radf_t + (l & 7)  * RSTR) + w * 8;
            u64 accA = 0ULL, accB = 0ULL;   // packed {even, odd} accumulators
            #pragma unroll
            for (int t = 0; t < 8; ++t) {
                ulonglong2 P = pp[t];
                ulonglong2 Q = rp[t];
                accA = fma2v(P.x, Q.x, accA);
                accB = fma2v(P.y, Q.y, accB);
            }
            u64 accT = fma2v(accA, 0x3f8000003f800000ULL, accB);  // accA*1 + accB
            float alo, ahi;
            unpack2(accT, alo, ahi);
            acc = alo + ahi;
        } else {
            const float4* pairdat = reinterpret_cast<const float4*>(radf_t);
            const float zk  = zetas[l];
            const float cak = cosAs[l];
            const float sak = sinAs[l];
            const float sZk = shfZs[l];
            const float e2k = etaA2s[l];   // negative
            #pragma unroll 4
            for (int p = w; p < 256; p += 8) {
                float4 pd = pairdat[p];
                float cosang = fmaf(pd.x, cak, pd.y * sak);
                float lg = lg2_approx(1.0f + cosang);
                float dd = pd.z - sZk;
                float e  = fmaf(zk, lg, (e2k * dd) * dd);
                acc = fmaf(ex2_approx(e), pd.w, acc);
            }
        }
        g3part[w][l] = acc;
    }
    __syncthreads();

    // ---- Phase 5: reduce + write output ----
    float* osite = out + (size_t)site * NF;
    if (tid < KA) {
        float s = 0.0f;
        #pragma unroll
        for (int ww = 0; ww < 8; ++ww) s += g3part[ww][tid];
        float scale = fast ? tb.outscale : two2s[tid];
        osite[KR + tid] = scale * s;
    }
    if (tid >= 64 && tid < 64 + KR) {
        const int k = tid - 64;
        float s = 0.0f;
        #pragma unroll
        for (int ww = 0; ww < 8; ++ww) s += g2part[ww][k];
        osite[k] = s;
    }
}

extern "C" void kernel_launch(void* const* d_in, const int* in_sizes, int n_in,
                              void* d_out, int out_size) {
    const float* coords     = (const float*)d_in[0];
    const int*   atom_types = (const int*)  d_in[1];
    const float* EtaR       = (const float*)d_in[2];
    const float* ShfR       = (const float*)d_in[3];
    const float* Zeta       = (const float*)d_in[4];
    const float* ShfZ       = (const float*)d_in[5];
    const float* EtaA       = (const float*)d_in[6];
    const float* ShfA       = (const float*)d_in[7];
    float* out = (float*)d_out;

    int T = in_sizes[2] / KR;
    if (T < 1) T = 1;
    if (T > MAXT) T = MAXT;

    ani_param_kernel<<<T, 32>>>(EtaR, ShfR, Zeta, ShfZ, EtaA, ShfA);
    ani_feature_kernel<<<BB * NA, 256>>>(coords, atom_types, out);
}

// round 8
// speedup vs baseline: 1.1234x; 1.1234x over previous
#include <cuda_runtime.h>
#include <math.h>

// Problem constants (fixed by the reference setup)
#define BB   256
#define NA   24      // atoms
#define NN   23      // neighbors per atom (N-1)
#define NP   253     // pairs = NN*(NN-1)/2
#define KR   16
#define KA   32
#define NF   (KR + KA)
#define RCR  5.2f
#define RCA  3.5f
#define PI_F 3.14159265358979323846f
#define LOG2E 1.4426950408889634f

#define PSTR 264     // pow_t row stride in floats (264 % 32 == 8  -> staggered banks)
#define RSTR 260     // radf_t row stride in floats (260 % 32 == 4 -> staggered banks)
#define SCALE_UP 100.0f
#define SCALE_DN 7.888609052210118e-31f   // 2^-100

typedef unsigned long long u64;

static __device__ __forceinline__ float ex2_approx(float x) {
    float r; asm("ex2.approx.ftz.f32 %0, %1;" : "=f"(r) : "f"(x)); return r;
}
static __device__ __forceinline__ float lg2_approx(float x) {
    float r; asm("lg2.approx.ftz.f32 %0, %1;" : "=f"(r) : "f"(x)); return r;
}
// ---- packed f32x2 helpers (sm_103a; ptxas never emits these from C++) ----
static __device__ __forceinline__ u64 pack2(float lo, float hi) {
    u64 r; asm("mov.b64 %0, {%1, %2};" : "=l"(r) : "f"(lo), "f"(hi)); return r;
}
static __device__ __forceinline__ void unpack2(u64 v, float& lo, float& hi) {
    asm("mov.b64 {%0, %1}, %2;" : "=f"(lo), "=f"(hi) : "l"(v));
}
static __device__ __forceinline__ u64 mul2(u64 a, u64 b) {
    u64 d; asm("mul.rn.f32x2 %0, %1, %2;" : "=l"(d) : "l"(a), "l"(b)); return d;
}
static __device__ __forceinline__ u64 fma2v(u64 a, u64 b, u64 c) {
    u64 d; asm("fma.rn.f32x2 %0, %1, %2, %3;" : "=l"(d) : "l"(a), "l"(b), "l"(c)); return d;
}

// Compile-time pair table: pair p -> (r | c<<8), rows of triu_indices(NN, k=1)
struct PT { unsigned short v[256]; };
static constexpr PT make_pt() {
    PT t{};
    int p = 0;
    for (int r = 0; r < NN; ++r)
        for (int c = r + 1; c < NN; ++c) { t.v[p] = (unsigned short)(r | (c << 8)); ++p; }
    for (; p < 256; ++p) t.v[p] = (unsigned short)(0 | (1 << 8));  // padding pairs
    return t;
}
static __device__ const PT d_pt = make_pt();

__global__ __launch_bounds__(256)
void ani_feature_kernel(const float* __restrict__ coords,     // (B, NA, 3)
                        const int*   __restrict__ atom_types, // (NA,)
                        const float* __restrict__ EtaR,       // (T, KR)
                        const float* __restrict__ ShfR,
                        const float* __restrict__ Zeta,       // (T, KA)
                        const float* __restrict__ ShfZ,
                        const float* __restrict__ EtaA,
                        const float* __restrict__ ShfA,
                        float*       __restrict__ out)        // (B, NA, 48)
{
    const int site = blockIdx.x;           // b * NA + i
    const int b = site / NA;
    const int i = site - b * NA;
    const int tid = threadIdx.x;
    const int w = tid >> 5;
    const int l = tid & 31;

    __shared__ __align__(16) float4 nb1[NN];   // {rx, ry, rz, invd}
    __shared__ __align__(8)  float2 nb2[NN];   // {d, fA}
    __shared__ __align__(8)  float2 nb3[NN];   // {d, fR}
    // Packed fast-path constants (read as float4 blocks in phase 3):
    //  [0..3]=cp  [4..7]=sp  [8]=s0 [9]=eA [10]=c1 [11]=rr0
    //  [12..17]=S0..S5  [18]=outscale  [19]=pad
    __shared__ __align__(16) float cpk[20];
    __shared__ float rrS[7];
    __shared__ int   sflagS;
    // Fallback generic tables (written only on the slow path)
    __shared__ float cosAs[KA], sinAs[KA], zetas[KA], shfZs[KA], etaA2s[KA], two2s[KA];
    __shared__ float g2part[8][KR];
    __shared__ float g3part[8][KA];
    __shared__ __align__(16) float pow_t[4 * PSTR];   // (1+cos(theta-a))^32, row a
    __shared__ __align__(16) float radf_t[8 * RSTR];  // exp(-eta(dz-s_z)^2)*fw, row z

    const int ti = atom_types[i];          // uniform broadcast LDG

    // ---- Phase 1 (warp 0): neighbor geometry ----
    if (tid < NN) {
        const int j = (tid < i) ? tid : tid + 1;
        const float* ci = coords + (size_t)(b * NA + i) * 3;
        const float* cj = coords + (size_t)(b * NA + j) * 3;
        float rx = ci[0] - cj[0];
        float ry = ci[1] - cj[1];
        float rz = ci[2] - cj[2];
        float d  = sqrtf(rx * rx + ry * ry + rz * rz);
        float fR = 0.5f * (cosf(d * (PI_F / RCR)) + 1.0f);
        float fA = 0.5f * (cosf(d * (PI_F / RCA)) + 1.0f);
        nb1[tid] = make_float4(rx, ry, rz, __frcp_rn(d));
        nb2[tid] = make_float2(d, fA);
        nb3[tid] = make_float2(d, fR);
    }

    // ---- Phase 1b (warp 2): structure checks + derived constants ----
    if (tid >= 64 && tid < 96) {
        const int k = tid - 64;
        const float* Zt  = Zeta + (size_t)ti * KA;
        const float* SZt = ShfZ + (size_t)ti * KA;
        const float* EAt = EtaA + (size_t)ti * KA;
        const float* SAt = ShfA + (size_t)ti * KA;
        float sz0 = SZt[0];
        float dlt = (SZt[7] - sz0) * (1.0f / 7.0f);
        float z   = Zt[k];
        float eA0 = EAt[0];
        bool ok = (z == 32.0f)
               && (EAt[k] == eA0)
               && (SAt[k] == SAt[k & ~7])
               && (SZt[k] == SZt[k & 7])
               && (fabsf(SZt[k & 7] - (sz0 + (float)(k & 7) * dlt)) < 1e-4f);
        unsigned m = __ballot_sync(0xffffffffu, ok);
        if (k == 0) sflagS = (m == 0xffffffffu);
        if (m == 0xffffffffu) {
            float eA = eA0 * LOG2E;
            if (k < 4) {
                float s, c; sincosf(SAt[k * 8], &s, &c);
                cpk[k] = c; cpk[4 + k] = s;
            }
            if (k >= 8 && k < 15) {
                float ed2 = eA * dlt * dlt;
                rrS[k - 8] = exp2f(-ed2 * (float)(2 * (k - 8) + 1));
            }
            if (k == 16) { cpk[8] = sz0; cpk[9] = eA; cpk[10] = 2.0f * eA * dlt; }
            if (k == 17) { cpk[18] = exp2f(1.0f - Zt[0]); cpk[19] = 0.0f; }
            __syncwarp();
            if (k < 6)  cpk[12 + k] = rrS[k] * rrS[k + 1];
            if (k == 6) cpk[11] = rrS[0];
        } else {
            float a = SAt[k];
            float s, c; sincosf(a, &s, &c);
            cosAs[k]  = c;  sinAs[k] = s;
            zetas[k]  = z;  two2s[k] = exp2f(1.0f - z);
            shfZs[k]  = SZt[k];
            etaA2s[k] = -EAt[k] * LOG2E;
        }
    }
    __syncthreads();

    const int fast = sflagS;

    // ---- Phase 2: radial G2 (per-warp partials) ----
    if (l < KR) {
        const float er = EtaR[ti * KR + l], sr = ShfR[ti * KR + l];
        float acc2 = 0.0f;
        for (int j = w; j < NN; j += 8) {
            float2 dr = nb3[j];                 // broadcast LDS.64
            float t = dr.x - sr;
            acc2 += __expf(-er * t * t) * dr.y;
        }
        g2part[w][l] = acc2;
    }

    // ---- Phase 3: per-pair geometry + specials (1 thread = 1 pair) ----
    {
        const int p = tid;                      // 0..255; 253..255 padding (fw = 0)
        const unsigned short rc = d_pt.v[p];
        const int r = rc & 0xFF, c = rc >> 8;
        float4 A1 = nb1[r];
        float4 B1 = nb1[c];
        float2 A2 = nb2[r];
        float2 B2 = nb2[c];
        float dot = A1.x * B1.x + A1.y * B1.y + A1.z * B1.z;
        float cs = dot * A1.w * B1.w;
        cs = fminf(fmaxf(cs, -1.0f + 1e-7f), 1.0f - 1e-7f);
        float sn = sqrtf(fmaxf(0.0f, 1.0f - cs * cs));
        float dz = 0.5f * (A2.x + B2.x);
        float fw = (p < NP) ? A2.y * B2.y : 0.0f;

        if (fast) {
            const float4 c4 = *reinterpret_cast<const float4*>(&cpk[0]);
            const float4 s4 = *reinterpret_cast<const float4*>(&cpk[4]);
            const float4 L4 = *reinterpret_cast<const float4*>(&cpk[8]);   // s0,eA,c1,rr0
            const float4 Sa = *reinterpret_cast<const float4*>(&cpk[12]);  // S0..S3
            const float4 Sb = *reinterpret_cast<const float4*>(&cpk[16]);  // S4,S5,outscale

            // 4 angular powers (1+cos(theta-a))^32 via packed repeated squaring
            const u64 ONE2 = 0x3f8000003f800000ULL;
            u64 cs2 = pack2(cs, cs), sn2 = pack2(sn, sn);
            u64 x01 = fma2v(cs2, pack2(c4.x, c4.y), fma2v(sn2, pack2(s4.x, s4.y), ONE2));
            u64 x23 = fma2v(cs2, pack2(c4.z, c4.w), fma2v(sn2, pack2(s4.z, s4.w), ONE2));
            x01 = mul2(x01, x01); x01 = mul2(x01, x01); x01 = mul2(x01, x01);
            x01 = mul2(x01, x01); x01 = mul2(x01, x01);
            x23 = mul2(x23, x23); x23 = mul2(x23, x23); x23 = mul2(x23, x23);
            x23 = mul2(x23, x23); x23 = mul2(x23, x23);
            float p0, p1, p2, p3;
            unpack2(x01, p0, p1); unpack2(x23, p2, p3);
            pow_t[0 * PSTR + p] = p0;  pow_t[1 * PSTR + p] = p1;
            pow_t[2 * PSTR + p] = p2;  pow_t[3 * PSTR + p] = p3;

            // 8 radial envelopes: 2^100-scaled geometric ladder, z+2 packed steps
            float u = dz - L4.x;
            float A = ex2_approx(fmaf(-L4.y * u, u, SCALE_UP));
            float R = ex2_approx(L4.z * u);
            float unsc = fw * SCALE_DN;
            float v0 = A * unsc;
            float v1 = v0 * R * L4.w;
            float R2 = R * R;
            u64 v01 = pack2(v0, v1);
            u64 v23 = mul2(v01, pack2(R2 * Sa.x, R2 * Sa.y));
            u64 v45 = mul2(v23, pack2(R2 * Sa.z, R2 * Sa.w));
            u64 v67 = mul2(v45, pack2(R2 * Sb.x, R2 * Sb.y));
            float f2, f3, f4, f5, f6, f7;
            unpack2(v23, f2, f3); unpack2(v45, f4, f5); unpack2(v67, f6, f7);
            radf_t[0 * RSTR + p] = v0;  radf_t[1 * RSTR + p] = v1;
            radf_t[2 * RSTR + p] = f2;  radf_t[3 * RSTR + p] = f3;
            radf_t[4 * RSTR + p] = f4;  radf_t[5 * RSTR + p] = f5;
            radf_t[6 * RSTR + p] = f6;  radf_t[7 * RSTR + p] = f7;
        } else {
            reinterpret_cast<float4*>(radf_t)[p] = make_float4(cs, sn, dz, fw);
        }
    }
    __syncthreads();

    // ---- Phase 4: angular accumulation ----
    {
        float acc = 0.0f;
        if (fast) {
            // lane l = feature (a = l/8, z = l%8); warp w covers pairs [32w, 32w+32)
            const ulonglong2* pp = reinterpret_cast<const ulonglong2*>(pow_t  + (l >> 3) * PSTR) + w * 8;
            const ulonglong2* rp = reinterpret_cast<const ulonglong2*>(radf_t + (l & 7)  * RSTR) + w * 8;
            u64 accA = 0ULL, accB = 0ULL;   // packed {even, odd} accumulators
            #pragma unroll
            for (int t = 0; t < 8; ++t) {
                ulonglong2 P = pp[t];
                ulonglong2 Q = rp[t];
                accA = fma2v(P.x, Q.x, accA);
                accB = fma2v(P.y, Q.y, accB);
            }
            u64 accT = fma2v(accA, 0x3f8000003f800000ULL, accB);  // accA*1 + accB
            float alo, ahi;
            unpack2(accT, alo, ahi);
            acc = alo + ahi;
        } else {
            const float4* pairdat = reinterpret_cast<const float4*>(radf_t);
            const float zk  = zetas[l];
            const float cak = cosAs[l];
            const float sak = sinAs[l];
            const float sZk = shfZs[l];
            const float e2k = etaA2s[l];   // negative
            #pragma unroll 4
            for (int p = w; p < 256; p += 8) {
                float4 pd = pairdat[p];
                float cosang = fmaf(pd.x, cak, pd.y * sak);
                float lg = lg2_approx(1.0f + cosang);
                float dd = pd.z - sZk;
                float e  = fmaf(zk, lg, (e2k * dd) * dd);
                acc = fmaf(ex2_approx(e), pd.w, acc);
            }
        }
        g3part[w][l] = acc;
    }
    __syncthreads();

    // ---- Phase 5: reduce + write output ----
    float* osite = out + (size_t)site * NF;
    if (tid < KA) {
        float s = 0.0f;
        #pragma unroll
        for (int ww = 0; ww < 8; ++ww) s += g3part[ww][tid];
        float scale = fast ? cpk[18] : two2s[tid];
        osite[KR + tid] = scale * s;
    }
    if (tid >= 64 && tid < 64 + KR) {
        const int k = tid - 64;
        float s = 0.0f;
        #pragma unroll
        for (int ww = 0; ww < 8; ++ww) s += g2part[ww][k];
        osite[k] = s;
    }
}

extern "C" void kernel_launch(void* const* d_in, const int* in_sizes, int n_in,
                              void* d_out, int out_size) {
    const float* coords     = (const float*)d_in[0];
    const int*   atom_types = (const int*)  d_in[1];
    const float* EtaR       = (const float*)d_in[2];
    const float* ShfR       = (const float*)d_in[3];
    const float* Zeta       = (const float*)d_in[4];
    const float* ShfZ       = (const float*)d_in[5];
    const float* EtaA       = (const float*)d_in[6];
    const float* ShfA       = (const float*)d_in[7];
    float* out = (float*)d_out;

    ani_feature_kernel<<<BB * NA, 256>>>(coords, atom_types, EtaR, ShfR, Zeta,
                                         ShfZ, EtaA, ShfA, out);
}

// round 9
// speedup vs baseline: 1.1689x; 1.0405x over previous
#include <cuda_runtime.h>
#include <math.h>

// Problem constants (fixed by the reference setup)
#define BB   256
#define NA   24      // atoms
#define NN   23      // neighbors per atom (N-1)
#define NP   253     // pairs = NN*(NN-1)/2
#define KR   16
#define KA   32
#define NF   (KR + KA)
#define RCR  5.2f
#define RCA  3.5f
#define PI_F 3.14159265358979323846f
#define LOG2E 1.4426950408889634f

#define SCALE_UP 100.0f
#define SCALE_DN 7.888609052210118e-31f   // 2^-100

typedef unsigned long long u64;

static __device__ __forceinline__ float ex2_approx(float x) {
    float r; asm("ex2.approx.ftz.f32 %0, %1;" : "=f"(r) : "f"(x)); return r;
}
static __device__ __forceinline__ float lg2_approx(float x) {
    float r; asm("lg2.approx.ftz.f32 %0, %1;" : "=f"(r) : "f"(x)); return r;
}
// ---- packed f32x2 helpers (sm_103a; ptxas never emits these from C++) ----
static __device__ __forceinline__ u64 pack2(float lo, float hi) {
    u64 r; asm("mov.b64 %0, {%1, %2};" : "=l"(r) : "f"(lo), "f"(hi)); return r;
}
static __device__ __forceinline__ void unpack2(u64 v, float& lo, float& hi) {
    asm("mov.b64 {%0, %1}, %2;" : "=f"(lo), "=f"(hi) : "l"(v));
}
static __device__ __forceinline__ u64 mul2(u64 a, u64 b) {
    u64 d; asm("mul.rn.f32x2 %0, %1, %2;" : "=l"(d) : "l"(a), "l"(b)); return d;
}
static __device__ __forceinline__ u64 fma2v(u64 a, u64 b, u64 c) {
    u64 d; asm("fma.rn.f32x2 %0, %1, %2, %3;" : "=l"(d) : "l"(a), "l"(b), "l"(c)); return d;
}

// Compile-time pair table: pair p -> (r | c<<8), rows of triu_indices(NN, k=1)
struct PT { unsigned short v[256]; };
static constexpr PT make_pt() {
    PT t{};
    int p = 0;
    for (int r = 0; r < NN; ++r)
        for (int c = r + 1; c < NN; ++c) { t.v[p] = (unsigned short)(r | (c << 8)); ++p; }
    for (; p < 256; ++p) t.v[p] = (unsigned short)(0 | (1 << 8));  // padding pairs
    return t;
}
static __device__ const PT d_pt = make_pt();

// Per-warp shared slab. Row stride 36 floats: phase-3 STS consecutive (conflict
// free), phase-4 LDS.128 rows land on disjoint bank groups ((4*row + 4t) % 32).
struct __align__(16) WarpBuf {
    float4 nb1[24];                       // {rx, ry, rz, invd}
    float2 nb2[24];                       // {d, fA}
    float2 nb3[24];                       // {d, fR}
    __align__(16) float powb[2][4 * 36];  // (1+cos(theta-a))^32, double buffered
    __align__(16) float radf[2][8 * 36];  // envelope ladder / fallback pairdat
};

__global__ __launch_bounds__(256)
void ani_feature_kernel(const float* __restrict__ coords,     // (B, NA, 3)
                        const int*   __restrict__ atom_types, // (NA,)
                        const float* __restrict__ EtaR,       // (T, KR)
                        const float* __restrict__ ShfR,
                        const float* __restrict__ Zeta,       // (T, KA)
                        const float* __restrict__ ShfZ,
                        const float* __restrict__ EtaA,
                        const float* __restrict__ ShfA,
                        float*       __restrict__ out)        // (B, NA, 48)
{
    const int warp = threadIdx.x >> 5;
    const int l    = threadIdx.x & 31;
    const int site = blockIdx.x * 8 + warp;    // one warp = one site
    const int b = site / NA;
    const int i = site - b * NA;

    __shared__ WarpBuf wb[8];
    WarpBuf& W = wb[warp];

    const int ti = atom_types[i];              // uniform broadcast LDG

    const float* Zt  = Zeta + (size_t)ti * KA;
    const float* SZt = ShfZ + (size_t)ti * KA;
    const float* EAt = EtaA + (size_t)ti * KA;
    const float* SAt = ShfA + (size_t)ti * KA;

    // ---- structure check (warp-uniform ballot) ----
    float sz0 = SZt[0];
    float dlt = (SZt[7] - sz0) * (1.0f / 7.0f);
    float eA0 = EAt[0];
    bool ok = (Zt[l] == 32.0f)
           && (EAt[l] == eA0)
           && (SAt[l] == SAt[l & ~7])
           && (SZt[l] == SZt[l & 7])
           && (fabsf(SZt[l & 7] - (sz0 + (float)(l & 7) * dlt)) < 1e-4f);
    const bool fast = (__ballot_sync(0xffffffffu, ok) == 0xffffffffu);

    // ---- derived constants (registers, via shuffle broadcast) ----
    float cA0, cA1, cA2, cA3, sA0, sA1, sA2, sA3;       // cos/sin of 4 ShfA values
    float eAc, c1c, rr0, S0, S1, S2, S3, S4, S5;
    // fallback per-lane feature params
    float zk = 0.f, cak = 0.f, sak = 0.f, sZk = 0.f, e2k = 0.f, two2k = 0.f;
    if (fast) {
        float sb, cb;
        sincosf(SAt[(l & 3) * 8], &sb, &cb);            // lanes 0..3 hold the 4 angles
        cA0 = __shfl_sync(0xffffffffu, cb, 0); sA0 = __shfl_sync(0xffffffffu, sb, 0);
        cA1 = __shfl_sync(0xffffffffu, cb, 1); sA1 = __shfl_sync(0xffffffffu, sb, 1);
        cA2 = __shfl_sync(0xffffffffu, cb, 2); sA2 = __shfl_sync(0xffffffffu, sb, 2);
        cA3 = __shfl_sync(0xffffffffu, cb, 3); sA3 = __shfl_sync(0xffffffffu, sb, 3);
        eAc = eA0 * LOG2E;
        c1c = 2.0f * eAc * dlt;
        float ed2 = eAc * dlt * dlt;
        float rr  = ex2_approx(-ed2 * (float)(2 * (l & 7) + 1));   // lanes 0..6 valid
        float Sv  = rr * __shfl_down_sync(0xffffffffu, rr, 1);
        rr0 = __shfl_sync(0xffffffffu, rr, 0);
        S0 = __shfl_sync(0xffffffffu, Sv, 0); S1 = __shfl_sync(0xffffffffu, Sv, 1);
        S2 = __shfl_sync(0xffffffffu, Sv, 2); S3 = __shfl_sync(0xffffffffu, Sv, 3);
        S4 = __shfl_sync(0xffffffffu, Sv, 4); S5 = __shfl_sync(0xffffffffu, Sv, 5);
    } else {
        zk  = Zt[l];
        sZk = SZt[l];
        e2k = -EAt[l] * LOG2E;
        sincosf(SAt[l], &sak, &cak);
        two2k = exp2f(1.0f - zk);
        eAc = c1c = rr0 = S0 = S1 = S2 = S3 = S4 = S5 = 0.f;
        cA0 = cA1 = cA2 = cA3 = sA0 = sA1 = sA2 = sA3 = 0.f;
    }

    // ---- Phase 1: neighbor geometry (lanes 0..22) ----
    if (l < NN) {
        const int j = (l < i) ? l : l + 1;
        const float* ci = coords + (size_t)(b * NA + i) * 3;
        const float* cj = coords + (size_t)(b * NA + j) * 3;
        float rx = ci[0] - cj[0];
        float ry = ci[1] - cj[1];
        float rz = ci[2] - cj[2];
        float d  = sqrtf(rx * rx + ry * ry + rz * rz);
        float fR = 0.5f * (cosf(d * (PI_F / RCR)) + 1.0f);
        float fA = 0.5f * (cosf(d * (PI_F / RCA)) + 1.0f);
        W.nb1[l] = make_float4(rx, ry, rz, __frcp_rn(d));
        W.nb2[l] = make_float2(d, fA);
        W.nb3[l] = make_float2(d, fR);
    }
    __syncwarp();

    // ---- Phase 2: radial G2 (lane = feature l%16, half = l/16; shfl combine) ----
    float g2acc = 0.0f;
    {
        const int k = l & 15;
        const float er = EtaR[ti * KR + k], sr = ShfR[ti * KR + k];
        for (int j = (l >> 4); j < NN; j += 2) {
            float2 df = W.nb3[j];
            float t = df.x - sr;
            g2acc += __expf(-er * t * t) * df.y;
        }
        g2acc += __shfl_xor_sync(0xffffffffu, g2acc, 16);
    }

    // ---- Phase 3+4: chunked pair loop, double buffered, 1 syncwarp/chunk ----
    u64 accA = 0ULL, accB = 0ULL;     // fast-path packed accumulators
    float accF = 0.0f;                // fallback accumulator
    #pragma unroll 2
    for (int ch = 0; ch < 8; ++ch) {
        const int par = ch & 1;
        const int p = ch * 32 + l;
        const unsigned short rc = d_pt.v[p];
        const int r = rc & 0xFF, c = rc >> 8;
        float4 A1 = W.nb1[r];
        float4 B1 = W.nb1[c];
        float2 A2 = W.nb2[r];
        float2 B2 = W.nb2[c];
        float dot = A1.x * B1.x + A1.y * B1.y + A1.z * B1.z;
        float cs = dot * A1.w * B1.w;
        cs = fminf(fmaxf(cs, -1.0f + 1e-7f), 1.0f - 1e-7f);
        float sn = sqrtf(fmaxf(0.0f, 1.0f - cs * cs));
        float dz = 0.5f * (A2.x + B2.x);
        float fw = (p < NP) ? A2.y * B2.y : 0.0f;

        if (fast) {
            // 4 angular powers (1+cos(theta-a))^32 via packed repeated squaring
            const u64 ONE2 = 0x3f8000003f800000ULL;
            u64 cs2 = pack2(cs, cs), sn2 = pack2(sn, sn);
            u64 x01 = fma2v(cs2, pack2(cA0, cA1), fma2v(sn2, pack2(sA0, sA1), ONE2));
            u64 x23 = fma2v(cs2, pack2(cA2, cA3), fma2v(sn2, pack2(sA2, sA3), ONE2));
            x01 = mul2(x01, x01); x01 = mul2(x01, x01); x01 = mul2(x01, x01);
            x01 = mul2(x01, x01); x01 = mul2(x01, x01);
            x23 = mul2(x23, x23); x23 = mul2(x23, x23); x23 = mul2(x23, x23);
            x23 = mul2(x23, x23); x23 = mul2(x23, x23);
            float p0, p1, p2, p3;
            unpack2(x01, p0, p1); unpack2(x23, p2, p3);
            float* pw = W.powb[par];
            pw[0 * 36 + l] = p0;  pw[1 * 36 + l] = p1;
            pw[2 * 36 + l] = p2;  pw[3 * 36 + l] = p3;

            // 8 radial envelopes: 2^100-scaled geometric ladder (2 MUFU)
            float u = dz - sz0;
            float A = ex2_approx(fmaf(-eAc * u, u, SCALE_UP));
            float R = ex2_approx(c1c * u);
            float unsc = fw * SCALE_DN;
            float v0 = A * unsc;
            float v1 = v0 * R * rr0;
            float R2 = R * R;
            u64 v01 = pack2(v0, v1);
            u64 v23 = mul2(v01, pack2(R2 * S0, R2 * S1));
            u64 v45 = mul2(v23, pack2(R2 * S2, R2 * S3));
            u64 v67 = mul2(v45, pack2(R2 * S4, R2 * S5));
            float f2, f3, f4, f5, f6, f7;
            unpack2(v23, f2, f3); unpack2(v45, f4, f5); unpack2(v67, f6, f7);
            float* rf = W.radf[par];
            rf[0 * 36 + l] = v0;  rf[1 * 36 + l] = v1;
            rf[2 * 36 + l] = f2;  rf[3 * 36 + l] = f3;
            rf[4 * 36 + l] = f4;  rf[5 * 36 + l] = f5;
            rf[6 * 36 + l] = f6;  rf[7 * 36 + l] = f7;
        } else {
            reinterpret_cast<float4*>(W.radf[par])[l] = make_float4(cs, sn, dz, fw);
        }
        __syncwarp();

        if (fast) {
            // lane l = feature (a = l/8, z = l%8) over this chunk's 32 pairs
            const ulonglong2* pp =
                reinterpret_cast<const ulonglong2*>(W.powb[par] + (l >> 3) * 36);
            const ulonglong2* rp =
                reinterpret_cast<const ulonglong2*>(W.radf[par] + (l & 7) * 36);
            #pragma unroll
            for (int t = 0; t < 8; ++t) {
                ulonglong2 P = pp[t];
                ulonglong2 Q = rp[t];
                accA = fma2v(P.x, Q.x, accA);
                accB = fma2v(P.y, Q.y, accB);
            }
        } else {
            const float4* pairdat = reinterpret_cast<const float4*>(W.radf[par]);
            #pragma unroll 4
            for (int q = 0; q < 32; ++q) {
                float4 pd = pairdat[q];
                float cosang = fmaf(pd.x, cak, pd.y * sak);
                float lg = lg2_approx(1.0f + cosang);
                float dd = pd.z - sZk;
                float e  = fmaf(zk, lg, (e2k * dd) * dd);
                accF = fmaf(ex2_approx(e), pd.w, accF);
            }
        }
        // no trailing syncwarp: next chunk writes the other buffer; this
        // chunk's reads are ordered before the next syncwarp in program order.
    }

    // ---- Phase 5: output (fully warp-local) ----
    float* osite = out + (size_t)site * NF;
    if (fast) {
        float a0, a1, b0, b1;
        unpack2(accA, a0, a1);
        unpack2(accB, b0, b1);
        osite[KR + l] = 0x1p-31f * ((a0 + a1) + (b0 + b1));  // 2^(1-zeta), zeta=32
    } else {
        osite[KR + l] = two2k * accF;
    }
    if (l < KR) osite[l] = g2acc;
}

extern "C" void kernel_launch(void* const* d_in, const int* in_sizes, int n_in,
                              void* d_out, int out_size) {
    const float* coords     = (const float*)d_in[0];
    const int*   atom_types = (const int*)  d_in[1];
    const float* EtaR       = (const float*)d_in[2];
    const float* ShfR       = (const float*)d_in[3];
    const float* Zeta       = (const float*)d_in[4];
    const float* ShfZ       = (const float*)d_in[5];
    const float* EtaA       = (const float*)d_in[6];
    const float* ShfA       = (const float*)d_in[7];
    float* out = (float*)d_out;

    ani_feature_kernel<<<(BB * NA) / 8, 256>>>(coords, atom_types, EtaR, ShfR,
                                               Zeta, ShfZ, EtaA, ShfA, out);
}